// round 13
// baseline (speedup 1.0000x reference)
#include <cuda_runtime.h>
#include <math.h>

// Problem shape (from reference setup_inputs): B=64, C=256, H=32, W=128
#define BB 64
#define CC 256
#define NROWS (BB * CC)  // 16384 (b,c) rows
#define HW 4096          // H*W
#define HW4 (HW / 4)     // float4 count per (b,c) row
#define ND 8             // NUM_DOMAINS
#define EPSV 1e-5f

// Scratch: per-sample channel sums. Fully overwritten every call.
__device__ float g_s [NROWS];
__device__ float g_sq[NROWS];

// Grid-barrier state. Sense-reversal: count returns to 0 after each barrier,
// sense flips once per launch -> consistent across graph replays.
__device__ unsigned int          g_bar_count;   // zero-initialized
__device__ volatile unsigned int g_bar_sense;   // zero-initialized

// ---------------------------------------------------------------------------
// Fused persistent kernel. Grid = exactly one resident wave (host computes it
// from the occupancy API), so the software grid barrier cannot deadlock.
//
// Phase 1: grid-stride ASCENDING row reduction -> g_s/g_sq. Blocks progress
//          in rough lockstep, so global read order is ascending by chunk and
//          the x-TAIL is L2-resident at phase end.
// Barrier: release/acquire grid sync.
// Phase 2: grid-stride DESCENDING rows: per-row (domain, channel) segment
//          stats from the tiny L2-resident tables, then FMA + __stcs
//          streaming stores (out is never re-read; don't let the 256 MB
//          write stream displace x residue).
// ---------------------------------------------------------------------------
__global__ __launch_bounds__(256, 6)
void fused_bn_kernel(const float* __restrict__ x,
                     const float* __restrict__ weight,
                     const float* __restrict__ bias,
                     const int*   __restrict__ domain_ids,
                     float*       __restrict__ out) {
    const int G  = gridDim.x;
    const int bi = blockIdx.x;
    const int t  = threadIdx.x;
    const int wid = t >> 5, lid = t & 31;

    __shared__ float sh_s[8], sh_sq[8];
    __shared__ float sh_red[6];
    __shared__ float sh_sc, sh_sh;
    __shared__ unsigned int sh_sense;

    // Snapshot barrier sense before any arrivals this launch.
    if (t == 0) sh_sense = g_bar_sense;
    __syncthreads();
    const unsigned int new_sense = sh_sense ^ 1u;

    // ---------------- Phase 1: row reductions (ascending) ----------------
    for (int row = bi; row < NROWS; row += G) {
        const float4* __restrict__ p =
            reinterpret_cast<const float4*>(x + (size_t)row * HW);

        float s = 0.f, sq = 0.f;
#pragma unroll
        for (int i = 0; i < HW4 / 256; ++i) {
            float4 v = p[t + i * 256];
            s  += (v.x + v.y) + (v.z + v.w);
            sq += (v.x * v.x + v.y * v.y) + (v.z * v.z + v.w * v.w);
        }
#pragma unroll
        for (int off = 16; off > 0; off >>= 1) {
            s  += __shfl_down_sync(0xffffffffu, s,  off);
            sq += __shfl_down_sync(0xffffffffu, sq, off);
        }
        if (lid == 0) { sh_s[wid] = s; sh_sq[wid] = sq; }
        __syncthreads();
        if (wid == 0) {
            s  = (lid < 8) ? sh_s [lid] : 0.f;
            sq = (lid < 8) ? sh_sq[lid] : 0.f;
#pragma unroll
            for (int off = 4; off > 0; off >>= 1) {
                s  += __shfl_down_sync(0xffffffffu, s,  off);
                sq += __shfl_down_sync(0xffffffffu, sq, off);
            }
            if (lid == 0) { g_s[row] = s; g_sq[row] = sq; }
        }
        __syncthreads();   // protect sh_s/sh_sq reuse next iteration
    }

    // ---------------- Grid barrier (sense-reversing) ----------------
    __syncthreads();
    if (t == 0) {
        __threadfence();   // release: g_s/g_sq visible before arrival
        unsigned int arrived = atomicAdd(&g_bar_count, 1u) + 1u;
        if (arrived == (unsigned int)G) {
            g_bar_count = 0u;
            __threadfence();
            g_bar_sense = new_sense;
        } else {
            while (g_bar_sense != new_sense) { }
            __threadfence();   // acquire: see all blocks' g_s/g_sq
        }
    }
    __syncthreads();

    // ---------------- Phase 2: stats + normalize (descending) ----------------
    for (int j = bi; j < NROWS; j += G) {
        const int row = (NROWS - 1) - j;
        const int b   = row >> 8;          // / CC
        const int c   = row & (CC - 1);    // % CC

        // per-row stats: segment-sum over the 64 samples for (domain(b), c)
        if (t < BB) {                      // 64 threads = 2 warps
            const int d_b = __ldg(&domain_ids[b]) - 1;
            const int d_t = __ldg(&domain_ids[t]) - 1;
            const bool m  = (d_t == d_b);
            float S  = m ? g_s [t * CC + c] : 0.f;
            float SQ = m ? g_sq[t * CC + c] : 0.f;
            float n  = m ? 1.f : 0.f;
#pragma unroll
            for (int off = 16; off > 0; off >>= 1) {
                S  += __shfl_down_sync(0xffffffffu, S,  off);
                SQ += __shfl_down_sync(0xffffffffu, SQ, off);
                n  += __shfl_down_sync(0xffffffffu, n,  off);
            }
            const int w = t >> 5, l = t & 31;
            if (l == 0) { sh_red[w] = S; sh_red[2 + w] = SQ; sh_red[4 + w] = n; }
        }
        __syncthreads();
        if (t == 0) {
            const float S    = sh_red[0] + sh_red[1];
            const float SQ   = sh_red[2] + sh_red[3];
            const float n    = sh_red[4] + sh_red[5];
            const float cnt  = fmaxf(n * (float)HW, 1.f);
            const float mean = S / cnt;
            const float var  = SQ / cnt - mean * mean;
            const float inv  = rsqrtf(var + EPSV);
            const float sc   = __ldg(&weight[c]) * inv;
            sh_sc = sc;
            sh_sh = __ldg(&bias[c]) - mean * sc;
        }
        __syncthreads();
        const float sc = sh_sc;
        const float sh = sh_sh;

        const float4* __restrict__ p =
            reinterpret_cast<const float4*>(x + (size_t)row * HW);
        float4* __restrict__ o =
            reinterpret_cast<float4*>(out + (size_t)row * HW);

#pragma unroll
        for (int i = 0; i < HW4 / 256; ++i) {
            float4 v = p[t + i * 256];        // default caching read
            v.x = fmaf(v.x, sc, sh);
            v.y = fmaf(v.y, sc, sh);
            v.z = fmaf(v.z, sc, sh);
            v.w = fmaf(v.w, sc, sh);
            __stcs(&o[t + i * 256], v);       // streaming store
        }
        // sh_red rewrites for the next iteration happen only after this
        // iteration's second __syncthreads -> no extra sync needed.
    }
}

extern "C" void kernel_launch(void* const* d_in, const int* in_sizes, int n_in,
                              void* d_out, int out_size) {
    const float* x          = (const float*)d_in[0];   // [B,C,H,W] fp32
    const float* weight     = (const float*)d_in[1];   // [C]
    const float* bias       = (const float*)d_in[2];   // [C]
    const int*   domain_ids = (const int*)  d_in[3];   // [B] int32, 1-based
    float*       out        = (float*)d_out;

    (void)in_sizes; (void)n_in; (void)out_size;

    // Exactly one resident wave -> software grid barrier is safe.
    int dev = 0, nsm = 0, maxb = 0;
    cudaGetDevice(&dev);
    cudaDeviceGetAttribute(&nsm, cudaDevAttrMultiProcessorCount, dev);
    cudaOccupancyMaxActiveBlocksPerMultiprocessor(&maxb, fused_bn_kernel, 256, 0);
    if (maxb < 1) maxb = 1;
    int grid = nsm * maxb;
    if (grid > NROWS) grid = NROWS;

    fused_bn_kernel<<<grid, 256>>>(x, weight, bias, domain_ids, out);
}

// round 14
// speedup vs baseline: 1.0555x; 1.0555x over previous
#include <cuda_runtime.h>
#include <math.h>

// Problem shape (from reference setup_inputs): B=64, C=256, H=32, W=128
#define BB 64
#define CC 256
#define HW 4096          // H*W
#define HW4 (HW / 4)     // float4 count per (b,c) row
#define ND 8             // NUM_DOMAINS
#define EPSV 1e-5f

// Scratch: per-sample channel sums. Fully overwritten every call.
__device__ float g_s [BB * CC];
__device__ float g_sq[BB * CC];

// ---------------------------------------------------------------------------
// Pass 1: per-(b,c) row reduction. One block per row, 256 threads, float4.
// Ascending block order + default (caching) loads -> at kernel end, L2
// holds the TAIL of x; pass 2 (descending) harvests it first.
// No explicit PDL trigger: the implicit per-block completion trigger lets
// pass 2's CTAs ramp up as this kernel drains.
// ---------------------------------------------------------------------------
__global__ __launch_bounds__(256) void row_reduce_kernel(const float* __restrict__ x) {
    const int bc = blockIdx.x;                       // 0 .. B*C-1
    const float4* __restrict__ p =
        reinterpret_cast<const float4*>(x + (size_t)bc * HW);
    const int t = threadIdx.x;

    float s = 0.f, sq = 0.f;
#pragma unroll
    for (int i = 0; i < HW4 / 256; ++i) {
        float4 v = p[t + i * 256];
        s  += (v.x + v.y) + (v.z + v.w);
        sq += (v.x * v.x + v.y * v.y) + (v.z * v.z + v.w * v.w);
    }

    // warp reduce
#pragma unroll
    for (int off = 16; off > 0; off >>= 1) {
        s  += __shfl_down_sync(0xffffffffu, s,  off);
        sq += __shfl_down_sync(0xffffffffu, sq, off);
    }

    __shared__ float sh_s[8], sh_sq[8];
    const int wid = t >> 5, lid = t & 31;
    if (lid == 0) { sh_s[wid] = s; sh_sq[wid] = sq; }
    __syncthreads();
    if (wid == 0) {
        s  = (lid < 8) ? sh_s [lid] : 0.f;
        sq = (lid < 8) ? sh_sq[lid] : 0.f;
#pragma unroll
        for (int off = 4; off > 0; off >>= 1) {
            s  += __shfl_down_sync(0xffffffffu, s,  off);
            sq += __shfl_down_sync(0xffffffffu, sq, off);
        }
        if (lid == 0) { g_s[bc] = s; g_sq[bc] = sq; }
    }
}

// ---------------------------------------------------------------------------
// Pass 2 (fused stats + normalize), PDL secondary. Descending block order
// to harvest pass 1's L2 tail residue.
//
// Per block:
//   0. cudaGridDependencySynchronize(): wait until pass 1 is fully complete
//      (g_s/g_sq valid). CTAs may already be resident on SMs that drained.
//   1. stats preamble: deterministic 64-sample segment reduce for (d, c)
//      from the tiny L2-resident g_s/g_sq tables. (Measured: fully hidden;
//      lean 28-reg body keeps occupancy high.)
//   2. FMA + streaming stores (__stcs: out is never re-read; keep its
//      256 MB write stream from displacing x residue).
// ---------------------------------------------------------------------------
__global__ __launch_bounds__(256) void norm_kernel(const float* __restrict__ x,
                                                   const float* __restrict__ weight,
                                                   const float* __restrict__ bias,
                                                   const int*   __restrict__ domain_ids,
                                                   float*       __restrict__ out) {
    const int bc = (BB * CC - 1) - blockIdx.x;   // descending row order
    const int b  = bc >> 8;          // / CC
    const int c  = bc & (CC - 1);    // % CC
    const int t  = threadIdx.x;

#if __CUDA_ARCH__ >= 900
    cudaGridDependencySynchronize();
#endif

    // --- 1. per-block stats: segment-sum over the 64 samples for (d, c) ---
    __shared__ float sh_red[6];      // [S0,S1, SQ0,SQ1, n0,n1] per-warp partials
    __shared__ float sh_sc, sh_sh;

    if (t < BB) {                    // 64 threads = 2 warps
        const int d_b  = __ldg(&domain_ids[b]) - 1;
        const int d_t  = __ldg(&domain_ids[t]) - 1;
        const bool m   = (d_t == d_b);
        float S  = m ? g_s [t * CC + c] : 0.f;
        float SQ = m ? g_sq[t * CC + c] : 0.f;
        float n  = m ? 1.f : 0.f;
#pragma unroll
        for (int off = 16; off > 0; off >>= 1) {
            S  += __shfl_down_sync(0xffffffffu, S,  off);
            SQ += __shfl_down_sync(0xffffffffu, SQ, off);
            n  += __shfl_down_sync(0xffffffffu, n,  off);
        }
        const int w = t >> 5, l = t & 31;
        if (l == 0) { sh_red[w] = S; sh_red[2 + w] = SQ; sh_red[4 + w] = n; }
    }
    __syncthreads();
    if (t == 0) {
        const float S    = sh_red[0] + sh_red[1];
        const float SQ   = sh_red[2] + sh_red[3];
        const float n    = sh_red[4] + sh_red[5];
        const float cnt  = fmaxf(n * (float)HW, 1.f);
        const float mean = S / cnt;
        const float var  = SQ / cnt - mean * mean;
        const float inv  = rsqrtf(var + EPSV);
        const float sc   = __ldg(&weight[c]) * inv;
        sh_sc = sc;
        sh_sh = __ldg(&bias[c]) - mean * sc;
    }
    __syncthreads();
    const float sc = sh_sc;
    const float sh = sh_sh;

    // --- 2. streaming normalize ---
    const float4* __restrict__ p =
        reinterpret_cast<const float4*>(x + (size_t)bc * HW);
    float4* __restrict__ o =
        reinterpret_cast<float4*>(out + (size_t)bc * HW);

#pragma unroll
    for (int i = 0; i < HW4 / 256; ++i) {
        float4 v = p[t + i * 256];                // default caching read
        v.x = fmaf(v.x, sc, sh);
        v.y = fmaf(v.y, sc, sh);
        v.z = fmaf(v.z, sc, sh);
        v.w = fmaf(v.w, sc, sh);
        __stcs(&o[t + i * 256], v);               // streaming store
    }
}

extern "C" void kernel_launch(void* const* d_in, const int* in_sizes, int n_in,
                              void* d_out, int out_size) {
    const float* x          = (const float*)d_in[0];   // [B,C,H,W] fp32
    const float* weight     = (const float*)d_in[1];   // [C]
    const float* bias       = (const float*)d_in[2];   // [C]
    const int*   domain_ids = (const int*)  d_in[3];   // [B] int32, 1-based
    float*       out        = (float*)d_out;

    (void)in_sizes; (void)n_in; (void)out_size;

    row_reduce_kernel<<<BB * CC, 256>>>(x);

    // Pass 2 with programmatic dependent launch: norm CTAs become resident
    // as pass 1's blocks drain; cudaGridDependencySynchronize() inside the
    // kernel orders the g_s/g_sq consumption after pass 1 completion.
    cudaLaunchConfig_t cfg = {};
    cfg.gridDim  = dim3(BB * CC);
    cfg.blockDim = dim3(256);
    cfg.dynamicSmemBytes = 0;
    cfg.stream = 0;
    cudaLaunchAttribute attrs[1];
    attrs[0].id = cudaLaunchAttributeProgrammaticStreamSerialization;
    attrs[0].val.programmaticStreamSerializationAllowed = 1;
    cfg.attrs = attrs;
    cfg.numAttrs = 1;
    cudaError_t e = cudaLaunchKernelEx(&cfg, norm_kernel,
                                       x, weight, bias, domain_ids, out);
    if (e != cudaSuccess) {
        // Fallback: plain launch (identical semantics, no overlap).
        norm_kernel<<<BB * CC, 256>>>(x, weight, bias, domain_ids, out);
    }
}